// round 9
// baseline (speedup 1.0000x reference)
#include <cuda_runtime.h>
#include <cuda_bf16.h>
#include <cstdint>

#define N_IN       16
#define FANIN      16
#define N_NODES    512
#define N_OUT      64
#define BATCH      32768
#define OUT_START  (N_NODES - N_OUT)   // node 448

#define THREADS    256
#define GRID       (BATCH / THREADS)   // 128 CTAs, one wave, 2 warps/SMSP

__device__ __forceinline__ float tanh_approx(float x) {
    float y; asm("tanh.approx.f32 %0, %1;" : "=f"(y) : "f"(x)); return y;
}

// Port-split weight storage:
//  - taps 0..3  : shared memory (1x LDS.128 per node)       [smem crossbar]
//  - taps 4..15 : __device__ global, L1-resident (3x LDG.128) [L1/LDG path]
//  - bias       : __constant__ (1x LDC.32, 2KB, cache-hot)   [const port]
// This breaks the single-port LDS bottleneck (wall tracked 4cyc x LDS-count/SM
// across R1/R2/R4/R8).
__constant__ float cB[N_NODES];                      // raw bias, 2 KB

// Folded weights for taps 4..15, row stride 12 floats (48 B, 16B-aligned).
__device__ __align__(16) float g_wfold[N_NODES * 12];

// Prep: fold source responses into weights for taps 4..15.
//   w'[node][t] = w[node][t] * resp[node + t - 16]   (identity for inputs)
__global__ void neat_prep(const float* __restrict__ w,
                          const float* __restrict__ resp)
{
    const int idx = blockIdx.x * blockDim.x + threadIdx.x;   // 0 .. 512*12-1
    if (idx >= N_NODES * 12) return;
    const int node = idx / 12;
    const int t    = idx % 12 + 4;
    const int g    = node + t;                                // global source
    const float s  = (g >= N_IN) ? resp[g - N_IN] : 1.0f;
    g_wfold[node * 12 + (t - 4)] = w[node * FANIN + t] * s;
}

__global__ void __launch_bounds__(THREADS, 1)
neat_forward_split(const float* __restrict__ x,
                   const float* __restrict__ w,      // [512][16]
                   const float* __restrict__ resp,   // [512]
                   float*       __restrict__ out)    // [BATCH][64]
{
    __shared__ __align__(16) float sh_w[N_NODES * 4];   // folded taps 0..3 (8 KB)
    __shared__ float sh_or[N_OUT];                      // resp of output nodes

    const int tid = threadIdx.x;

    // Fold taps 0..3 into smem.
    for (int i = tid; i < N_NODES * 4; i += THREADS) {
        const int node = i >> 2, t = i & 3;
        const int g = node + t;
        const float s = (g >= N_IN) ? resp[g - N_IN] : 1.0f;
        sh_w[i] = w[node * FANIN + t] * s;
    }
    for (int i = tid; i < N_OUT; i += THREADS) sh_or[i] = resp[OUT_START + i];
    __syncthreads();

    const int b = blockIdx.x * THREADS + tid;       // one batch element / thread

    // Circular register window: v[g & 15] = RAW tanh value at global index g
    // (inputs raw). Node i (j = i & 15) reads v[(j+t)&15], writes v[j].
    float v[16];
    {
        const float4* xv = (const float4*)(x + (size_t)b * N_IN);
        #pragma unroll
        for (int q = 0; q < 4; q++) {
            float4 t = xv[q];
            v[4*q+0] = t.x; v[4*q+1] = t.y; v[4*q+2] = t.z; v[4*q+3] = t.w;
        }
    }

    float* outp = out + (size_t)b * N_OUT;
    const float4* wg = (const float4*)g_wfold;      // 3 float4 per node

    #pragma unroll 1
    for (int g = 0; g < N_NODES / 16; g++) {
        #pragma unroll
        for (int j = 0; j < 16; j++) {
            const int node = g * 16 + j;

            // taps 0..3 from smem (1 LDS.128)
            const float4 q0 = *(const float4*)(sh_w + node * 4);
            // taps 4..15 from global via read-only path (3 LDG.128, L1-hot,
            // non-aliasing -> freely hoistable, deep MLP)
            const float4 q1 = __ldg(wg + node * 3 + 0);
            const float4 q2 = __ldg(wg + node * 3 + 1);
            const float4 q3 = __ldg(wg + node * 3 + 2);
            // bias from constant bank (1 LDC.32)
            const float  bb = cB[node];

            // Taps 0..14 depend on node-2 and older -> off the serial path.
            float a0 = fmaf(v[(j + 0)  & 15], q0.x, bb);
            float a1 =      v[(j + 1)  & 15] * q0.y;
            float a2 =      v[(j + 2)  & 15] * q0.z;
            float a3 =      v[(j + 3)  & 15] * q0.w;
            a0 = fmaf(v[(j + 4)  & 15], q1.x, a0);
            a1 = fmaf(v[(j + 5)  & 15], q1.y, a1);
            a2 = fmaf(v[(j + 6)  & 15], q1.z, a2);
            a3 = fmaf(v[(j + 7)  & 15], q1.w, a3);
            a0 = fmaf(v[(j + 8)  & 15], q2.x, a0);
            a1 = fmaf(v[(j + 9)  & 15], q2.y, a1);
            a2 = fmaf(v[(j + 10) & 15], q2.z, a2);
            a3 = fmaf(v[(j + 11) & 15], q2.w, a3);
            a0 = fmaf(v[(j + 12) & 15], q3.x, a0);
            a1 = fmaf(v[(j + 13) & 15], q3.y, a1);
            a2 = fmaf(v[(j + 14) & 15], q3.z, a2);
            const float partial = (a0 + a1) + (a2 + a3);

            // Serial path: ONE fma + tanh.
            const float agg = fmaf(v[(j + 15) & 15], q3.w, partial);
            const float y = tanh_approx(agg);
            v[j] = y;

            if (g >= OUT_START / 16) {
                const int o = node - OUT_START;
                outp[o] = y * sh_or[o];             // resp applied off-path
            }
        }
    }
}

extern "C" void kernel_launch(void* const* d_in, const int* in_sizes, int n_in,
                              void* d_out, int out_size) {
    const float* x    = (const float*)d_in[0];   // [BATCH, 16]
    const float* w    = (const float*)d_in[1];   // [512, 16]
    const float* bias = (const float*)d_in[2];   // [512]
    const float* resp = (const float*)d_in[3];   // [512]
    // d_in[4] (src_idx) is the fixed sliding-window topology; baked into indexing.
    float* out = (float*)d_out;                  // [BATCH, 64]

    // Bias -> constant bank (async D2D, graph-capturable).
    cudaMemcpyToSymbolAsync(cB, bias, N_NODES * sizeof(float), 0,
                            cudaMemcpyDeviceToDevice, 0);
    // Fold taps 4..15 into the global weight array (same stream, ordered).
    neat_prep<<<(N_NODES * 12 + 255) / 256, 256>>>(w, resp);
    // Main forward pass.
    neat_forward_split<<<GRID, THREADS>>>(x, w, resp, out);
}

// round 10
// speedup vs baseline: 1.6709x; 1.6709x over previous
#include <cuda_runtime.h>
#include <cuda_bf16.h>
#include <cstdint>

#define N_IN       16
#define FANIN      16
#define N_NODES    512
#define N_OUT      64
#define BATCH      32768
#define HALF       (BATCH / 2)          // 16384
#define OUT_START  (N_NODES - N_OUT)    // node 448

#define THREADS    128
#define GRID       (HALF / THREADS)     // 128 CTAs, 4 warps/SM = 1/SMSP

__device__ __forceinline__ float tanh_approx(float x) {
    float y; asm("tanh.approx.f32 %0, %1;" : "=f"(y) : "f"(x)); return y;
}

// Shared memory (float units):
//   [0, 8192)    : resp-folded weights w'[node][tap] = w*resp[src] (32 KB)
//   [8192, 8704) : bias per node (2 KB)
//   [8704, 8768) : resp for the 64 output nodes (256 B)
#define SMEM_W   0
#define SMEM_B   (N_NODES * FANIN)
#define SMEM_R   (SMEM_B + N_NODES)
#define SMEM_F32 (SMEM_R + N_OUT)

__global__ void __launch_bounds__(THREADS, 1)
neat_forward_2chain(const float* __restrict__ x,
                    const float* __restrict__ w,      // [512][16]
                    const float* __restrict__ bias,   // [512]
                    const float* __restrict__ resp,   // [512]
                    float*       __restrict__ out)    // [BATCH][64]
{
    extern __shared__ __align__(16) float sh[];
    const int tid = threadIdx.x;

    // Fold each source's response into the consumer weight:
    //   w'[i][t] = w[i][t] * resp[i + t - 16]   (identity for input sources).
    // The register windows carry RAW tanh values; resp applied only at stores.
    for (int i = tid; i < N_NODES * FANIN; i += THREADS) {
        const int node = i >> 4, t = i & 15;
        const int g = node + t;
        const float s = (g >= N_IN) ? resp[g - N_IN] : 1.0f;
        sh[SMEM_W + i] = w[i] * s;
    }
    for (int i = tid; i < N_NODES; i += THREADS) sh[SMEM_B + i] = bias[i];
    for (int i = tid; i < N_OUT;   i += THREADS) sh[SMEM_R + i] = resp[OUT_START + i];
    __syncthreads();

    // Two scalar chains per thread sharing one weight-load stream:
    // smem traffic/node/SM drops 136 -> 68 wavefronts (4 warps x (4xLDS.128 + 1)).
    const int b0 = blockIdx.x * THREADS + tid;
    const int b1 = b0 + HALF;

    // Circular register windows: v*[g & 15] = value at global index g.
    float va[16], vb[16];
    {
        const float4* x0 = (const float4*)(x + (size_t)b0 * N_IN);
        const float4* x1 = (const float4*)(x + (size_t)b1 * N_IN);
        #pragma unroll
        for (int q = 0; q < 4; q++) {
            float4 t0 = x0[q], t1 = x1[q];
            va[4*q+0] = t0.x; va[4*q+1] = t0.y; va[4*q+2] = t0.z; va[4*q+3] = t0.w;
            vb[4*q+0] = t1.x; vb[4*q+1] = t1.y; vb[4*q+2] = t1.z; vb[4*q+3] = t1.w;
        }
    }

    float* outp0 = out + (size_t)b0 * N_OUT;
    float* outp1 = out + (size_t)b1 * N_OUT;

    #pragma unroll 1
    for (int g = 0; g < N_NODES / 16; g++) {
        #pragma unroll
        for (int j = 0; j < 16; j++) {
            const int node = g * 16 + j;
            // ONE shared weight fetch serves both chains.
            const float4* wv = (const float4*)(sh + SMEM_W + node * FANIN);
            const float4 q0 = wv[0], q1 = wv[1], q2 = wv[2], q3 = wv[3];
            const float  bb = sh[SMEM_B + node];

            // ---- chain A ---- (taps 0..14 off the serial path; tap 15 last)
            float a0 = fmaf(va[(j + 0)  & 15], q0.x, bb);
            float a1 =      va[(j + 1)  & 15] * q0.y;
            float a2 =      va[(j + 2)  & 15] * q0.z;
            float a3 =      va[(j + 3)  & 15] * q0.w;
            // ---- chain B ----
            float c0 = fmaf(vb[(j + 0)  & 15], q0.x, bb);
            float c1 =      vb[(j + 1)  & 15] * q0.y;
            float c2 =      vb[(j + 2)  & 15] * q0.z;
            float c3 =      vb[(j + 3)  & 15] * q0.w;

            a0 = fmaf(va[(j + 4)  & 15], q1.x, a0);
            a1 = fmaf(va[(j + 5)  & 15], q1.y, a1);
            a2 = fmaf(va[(j + 6)  & 15], q1.z, a2);
            a3 = fmaf(va[(j + 7)  & 15], q1.w, a3);
            c0 = fmaf(vb[(j + 4)  & 15], q1.x, c0);
            c1 = fmaf(vb[(j + 5)  & 15], q1.y, c1);
            c2 = fmaf(vb[(j + 6)  & 15], q1.z, c2);
            c3 = fmaf(vb[(j + 7)  & 15], q1.w, c3);

            a0 = fmaf(va[(j + 8)  & 15], q2.x, a0);
            a1 = fmaf(va[(j + 9)  & 15], q2.y, a1);
            a2 = fmaf(va[(j + 10) & 15], q2.z, a2);
            a3 = fmaf(va[(j + 11) & 15], q2.w, a3);
            c0 = fmaf(vb[(j + 8)  & 15], q2.x, c0);
            c1 = fmaf(vb[(j + 9)  & 15], q2.y, c1);
            c2 = fmaf(vb[(j + 10) & 15], q2.z, c2);
            c3 = fmaf(vb[(j + 11) & 15], q2.w, c3);

            a0 = fmaf(va[(j + 12) & 15], q3.x, a0);
            a1 = fmaf(va[(j + 13) & 15], q3.y, a1);
            a2 = fmaf(va[(j + 14) & 15], q3.z, a2);
            c0 = fmaf(vb[(j + 12) & 15], q3.x, c0);
            c1 = fmaf(vb[(j + 13) & 15], q3.y, c1);
            c2 = fmaf(vb[(j + 14) & 15], q3.z, c2);

            const float pa = (a0 + a1) + (a2 + a3);
            const float pb = (c0 + c1) + (c2 + c3);

            // Serial path per chain: ONE fma + tanh (independent across chains).
            const float ya = tanh_approx(fmaf(va[(j + 15) & 15], q3.w, pa));
            const float yb = tanh_approx(fmaf(vb[(j + 15) & 15], q3.w, pb));
            va[j] = ya;
            vb[j] = yb;

            if (g >= OUT_START / 16) {
                const int o = node - OUT_START;
                const float r = sh[SMEM_R + o];
                outp0[o] = ya * r;                  // resp applied off-path
                outp1[o] = yb * r;
            }
        }
    }
}

extern "C" void kernel_launch(void* const* d_in, const int* in_sizes, int n_in,
                              void* d_out, int out_size) {
    const float* x    = (const float*)d_in[0];   // [BATCH, 16]
    const float* w    = (const float*)d_in[1];   // [512, 16]
    const float* bias = (const float*)d_in[2];   // [512]
    const float* resp = (const float*)d_in[3];   // [512]
    // d_in[4] (src_idx) is the fixed sliding-window topology; baked into indexing.
    float* out = (float*)d_out;                  // [BATCH, 64]

    const int smem_bytes = SMEM_F32 * (int)sizeof(float);   // ~34.3 KB
    neat_forward_2chain<<<GRID, THREADS, smem_bytes>>>(x, w, bias, resp, out);
}